// round 8
// baseline (speedup 1.0000x reference)
#include <cuda_runtime.h>

#define HW 4096  // 64*64
typedef unsigned long long ull;

// Device scratch
__device__ float g_act[4 * 64 * HW];      // [b][co=64][h][w]
__device__ float g_mask[4 * HW * 100];    // [b][pixel][k=25][s=4], softmaxed
__device__ float g_wt2[576 * 112];        // enc w: [t=ci*9+r][s=4][28pad]
__device__ float g_wct[256 * 64];         // comp w: [c][o]

// ---- f32x2 helpers -------------------------------------------------------
__device__ __forceinline__ void ffma2(ull& d, ull a, ull b) {
  asm("fma.rn.f32x2 %0, %1, %2, %0;" : "+l"(d) : "l"(a), "l"(b));
}
__device__ __forceinline__ ull dup2(float v) {
  ull d;
  asm("mov.b64 %0, {%1, %1};" : "=l"(d) : "r"(__float_as_uint(v)));
  return d;
}
__device__ __forceinline__ float lo32(ull d) { return __uint_as_float((unsigned)d); }
__device__ __forceinline__ float hi32(ull d) { return __uint_as_float((unsigned)(d >> 32)); }

// ---------------------------------------------------------------------------
// kW: one-time weight reorganization
// ---------------------------------------------------------------------------
__global__ void __launch_bounds__(256) kW(const float* __restrict__ wc,
                                          const float* __restrict__ we) {
  int idx = blockIdx.x * 256 + threadIdx.x;
  if (idx < 576 * 112) {
    int t = idx / 112;
    int rem = idx - t * 112;
    int s = rem / 28, k = rem - s * 28;
    g_wt2[idx] = (k < 25) ? we[(k * 4 + s) * 576 + t] : 0.f;
  }
  int j = idx - 576 * 112;
  if (j >= 0 && j < 256 * 64) {
    int c = j >> 6, o = j & 63;
    g_wct[j] = wc[o * 256 + c];
  }
}

// ---------------------------------------------------------------------------
// kA: 1x1 conv (256->64) + BN + SiLU, f32x2 packed over output pairs.
// Block = 64 px x 64 out, 128 threads; thread tile = 4 o-pairs x 4 px.
// ---------------------------------------------------------------------------
__global__ void __launch_bounds__(128) kA(
    const float* __restrict__ x,
    const float* __restrict__ gma, const float* __restrict__ bet,
    const float* __restrict__ mea, const float* __restrict__ var) {
  __shared__ float xs[64 * 64];
  __shared__ float ws[64 * 64];

  int blk = blockIdx.x;
  int b = blk >> 6;
  int p0 = (blk & 63) << 6;
  int tid = threadIdx.x;
  int pp = tid & 15;   // 4 pixels
  int po = tid >> 4;   // 8 outputs (4 pairs)

  ull acc[4][4];       // [o-pair][px]
#pragma unroll
  for (int a = 0; a < 4; a++)
#pragma unroll
    for (int p = 0; p < 4; p++) acc[a][p] = 0ull;

  const float* xb = x + (size_t)(b * 256) * HW + p0;

#pragma unroll 1
  for (int cc = 0; cc < 4; cc++) {
    __syncthreads();
    const float4* xg = (const float4*)(xb + (size_t)cc * 64 * HW);
    float4* xsd = (float4*)xs;
    for (int u = tid; u < 1024; u += 128) {
      int ci = u >> 4, m = u & 15;
      xsd[u] = xg[ci * 1024 + m];
    }
    const float4* wg = (const float4*)(g_wct + cc * 64 * 64);
    float4* wsd = (float4*)ws;
    for (int u = tid; u < 1024; u += 128) wsd[u] = wg[u];
    __syncthreads();

#pragma unroll 4
    for (int ci = 0; ci < 64; ci++) {
      float4 xv = *(const float4*)(xs + ci * 64 + pp * 4);
      ull xd[4] = {dup2(xv.x), dup2(xv.y), dup2(xv.z), dup2(xv.w)};
      const ull* wp = (const ull*)(ws + ci * 64 + po * 8);
#pragma unroll
      for (int op = 0; op < 4; op++) {
        ull w2 = wp[op];
#pragma unroll
        for (int p = 0; p < 4; p++) ffma2(acc[op][p], w2, xd[p]);
      }
    }
  }

  float* actb = g_act + (size_t)(b * 64) * HW + p0 + pp * 4;
#pragma unroll
  for (int op = 0; op < 4; op++) {
    int o = po * 8 + op * 2;
    float inv0 = gma[o] * rsqrtf(var[o] + 1e-5f);
    float off0 = bet[o] - mea[o] * inv0;
    float inv1 = gma[o + 1] * rsqrtf(var[o + 1] + 1e-5f);
    float off1 = bet[o + 1] - mea[o + 1] * inv1;
    float4 r0, r1;
    float v;
    v = lo32(acc[op][0]) * inv0 + off0; r0.x = v / (1.f + __expf(-v));
    v = lo32(acc[op][1]) * inv0 + off0; r0.y = v / (1.f + __expf(-v));
    v = lo32(acc[op][2]) * inv0 + off0; r0.z = v / (1.f + __expf(-v));
    v = lo32(acc[op][3]) * inv0 + off0; r0.w = v / (1.f + __expf(-v));
    v = hi32(acc[op][0]) * inv1 + off1; r1.x = v / (1.f + __expf(-v));
    v = hi32(acc[op][1]) * inv1 + off1; r1.y = v / (1.f + __expf(-v));
    v = hi32(acc[op][2]) * inv1 + off1; r1.z = v / (1.f + __expf(-v));
    v = hi32(acc[op][3]) * inv1 + off1; r1.w = v / (1.f + __expf(-v));
    *(float4*)(actb + (size_t)o * HW) = r0;
    *(float4*)(actb + (size_t)(o + 1) * HW) = r1;
  }
}

// ---------------------------------------------------------------------------
// kB: 3x3 conv (64->100ch) + softmax over k. f32x2 packed over adjacent k.
// Weight pairs (w[k],w[k+1]) read as LDS.64 from [t][s][28pad] layout.
// ---------------------------------------------------------------------------
__global__ void __launch_bounds__(128, 5) kB() {
  __shared__ float as_[6400];   // act tile [64][10][10]
  __shared__ float ws[4032];    // weight chunk [36][112]

  int b = blockIdx.z;
  int i0 = blockIdx.y << 3, j0 = blockIdx.x << 3;
  int tid = threadIdx.x;
  int s = tid & 3, q = tid >> 2;
  int ty = q >> 3, tx = q & 7;

  for (int idx = tid; idx < 6400; idx += 128) {
    int ci = idx / 100;
    int rem = idx - ci * 100;
    int rr = rem / 10, cc2 = rem - rr * 10;
    int gi = i0 + rr - 1, gj = j0 + cc2 - 1;
    float v = 0.f;
    if ((unsigned)gi < 64u && (unsigned)gj < 64u)
      v = g_act[((size_t)(b * 64 + ci)) * HW + (gi << 6) + gj];
    as_[idx] = v;
  }

  ull a0p[12], a1p[12];
  float a0t = 0.f, a1t = 0.f;
#pragma unroll
  for (int t = 0; t < 12; t++) { a0p[t] = 0ull; a1p[t] = 0ull; }

#pragma unroll 1
  for (int cc = 0; cc < 16; cc++) {
    __syncthreads();
    const float4* src = (const float4*)(g_wt2 + cc * 4032);
    float4* dstw = (float4*)ws;
    for (int u = tid; u < 1008; u += 128) dstw[u] = src[u];
    __syncthreads();
#pragma unroll 1
    for (int cl = 0; cl < 4; cl++) {
      const float* ap = as_ + (cc * 4 + cl) * 100;
#pragma unroll
      for (int r = 0; r < 9; r++) {
        int dy = r / 3, dx = r - dy * 3;
        float v0 = ap[(ty + dy) * 10 + tx + dx];
        float v1 = ap[(ty + 4 + dy) * 10 + tx + dx];
        ull v0d = dup2(v0), v1d = dup2(v1);
        int off = (cl * 9 + r) * 112 + s * 28;
        const ull* wp = (const ull*)(ws + off);
#pragma unroll
        for (int t = 0; t < 12; t++) {
          ull w2 = wp[t];
          ffma2(a0p[t], w2, v0d);
          ffma2(a1p[t], w2, v1d);
        }
        float wl = ws[off + 24];
        a0t += wl * v0;
        a1t += wl * v1;
      }
    }
  }

  // unpack + softmax + store (mask layout: [pixel][k][s])
  float acc0[25], acc1[25];
#pragma unroll
  for (int t = 0; t < 12; t++) {
    acc0[2 * t] = lo32(a0p[t]); acc0[2 * t + 1] = hi32(a0p[t]);
    acc1[2 * t] = lo32(a1p[t]); acc1[2 * t + 1] = hi32(a1p[t]);
  }
  acc0[24] = a0t; acc1[24] = a1t;

  int p0 = (i0 + ty) * 64 + (j0 + tx);
  int p1 = p0 + 256;
  {
    float m = acc0[0];
#pragma unroll
    for (int k = 1; k < 25; k++) m = fmaxf(m, acc0[k]);
    float ssum = 0.f;
#pragma unroll
    for (int k = 0; k < 25; k++) { acc0[k] = __expf(acc0[k] - m); ssum += acc0[k]; }
    float rs = 1.f / ssum;
    float* dst = g_mask + ((size_t)(b * HW + p0)) * 100 + s;
#pragma unroll
    for (int k = 0; k < 25; k++) dst[4 * k] = acc0[k] * rs;
  }
  {
    float m = acc1[0];
#pragma unroll
    for (int k = 1; k < 25; k++) m = fmaxf(m, acc1[k]);
    float ssum = 0.f;
#pragma unroll
    for (int k = 0; k < 25; k++) { acc1[k] = __expf(acc1[k] - m); ssum += acc1[k]; }
    float rs = 1.f / ssum;
    float* dst = g_mask + ((size_t)(b * HW + p1)) * 100 + s;
#pragma unroll
    for (int k = 0; k < 25; k++) dst[4 * k] = acc1[k] * rs;
  }
}

// ---------------------------------------------------------------------------
// kC: 5x5 unfold + mask-weighted sum + pixel shuffle, f32x2 packed over s.
// x tile duplicated in smem ((v,v) pairs -> LDS.64 gives packed operand).
// Mask [k][s] layout -> ulonglong2 load gives (s0,s1),(s2,s3) pre-packed.
// 16 channels/block.
// ---------------------------------------------------------------------------
__global__ void __launch_bounds__(128, 3) kC(const float* __restrict__ x,
                                             float* __restrict__ out) {
  extern __shared__ float xs2[];   // [16][6][136] duplicated = 13056 floats
  int gc0 = blockIdx.x << 4;
  int ri = blockIdx.y;
  int b = blockIdx.z;
  int tid = threadIdx.x;
  int r = tid >> 6, j = tid & 63;
  int i = (ri << 1) + r;

  const float* xb = x + ((size_t)(b * 256 + gc0)) * HW;
  // data region (cols 2..65 of 68, duplicated)
  for (int u = tid; u < 1536; u += 128) {
    int c = u / 96;
    int rem = u - c * 96;
    int lr = rem >> 4, m = rem & 15;
    int grow = (ri << 1) - 2 + lr;
    float4 v = make_float4(0.f, 0.f, 0.f, 0.f);
    if ((unsigned)grow < 64u)
      v = *(const float4*)(xb + (size_t)c * HW + (grow << 6) + m * 4);
    float* d = xs2 + c * 816 + lr * 136 + (2 + m * 4) * 2;
    *(float2*)(d + 0) = make_float2(v.x, v.x);
    *(float2*)(d + 2) = make_float2(v.y, v.y);
    *(float2*)(d + 4) = make_float2(v.z, v.z);
    *(float2*)(d + 6) = make_float2(v.w, v.w);
  }
  // halo cols {0,1,66,67} (duplicated) = zero
  for (int u = tid; u < 384; u += 128) {
    int c = u / 24;
    int rem = u - c * 24;
    int lr = rem / 4, side = rem & 3;   // side: 0,1 -> cols 0,1 ; 2,3 -> 66,67
    int col = (side < 2) ? side : (64 + side);
    *(float2*)(xs2 + c * 816 + lr * 136 + col * 2) = make_float2(0.f, 0.f);
  }
  __syncthreads();

  // mask pairs -> registers
  ull mk01[25], mk23[25];
  const ulonglong2* mp =
      (const ulonglong2*)(g_mask + ((size_t)(b * HW + (i << 6) + j)) * 100);
#pragma unroll
  for (int k = 0; k < 25; k++) {
    ulonglong2 v = mp[k];
    mk01[k] = v.x;   // (s=0, s=1)
    mk23[k] = v.y;   // (s=2, s=3)
  }

  float* ob = out + ((size_t)(b * 256 + gc0) * 128 + (i << 1)) * 128 + (j << 1);

#pragma unroll 1
  for (int c = 0; c < 16; c++) {
    const float* pq = xs2 + c * 816 + r * 136 + j * 2;
    ull acc01 = 0ull, acc23 = 0ull;
#pragma unroll
    for (int dy = 0; dy < 5; dy++) {
#pragma unroll
      for (int dx = 0; dx < 5; dx++) {
        ull pvv = *(const ull*)(pq + dy * 136 + dx * 2);
        int k = dy * 5 + dx;
        ffma2(acc01, mk01[k], pvv);
        ffma2(acc23, mk23[k], pvv);
      }
    }
    float* op = ob + (size_t)c * 128 * 128;
    *(float2*)op = make_float2(lo32(acc01), hi32(acc01));
    *(float2*)(op + 128) = make_float2(lo32(acc23), hi32(acc23));
  }
}

// ---------------------------------------------------------------------------
extern "C" void kernel_launch(void* const* d_in, const int* in_sizes, int n_in,
                              void* d_out, int out_size) {
  const float* x   = (const float*)d_in[0];
  const float* wc  = (const float*)d_in[1];
  const float* gma = (const float*)d_in[2];
  const float* bet = (const float*)d_in[3];
  const float* mea = (const float*)d_in[4];
  const float* var = (const float*)d_in[5];
  const float* we  = (const float*)d_in[6];
  float* out = (float*)d_out;

  int smC = 16 * 816 * 4;  // 52224
  cudaFuncSetAttribute(kC, cudaFuncAttributeMaxDynamicSharedMemorySize, smC);

  kW<<<(576 * 112 + 256 * 64 + 255) / 256, 256>>>(wc, we);
  kA<<<256, 128>>>(x, gma, bet, mea, var);
  kB<<<dim3(8, 8, 4), 128>>>();
  kC<<<dim3(16, 32, 4), 128, smC>>>(x, out);
}

// round 9
// speedup vs baseline: 1.1101x; 1.1101x over previous
#include <cuda_runtime.h>

#define HW 4096  // 64*64
typedef unsigned long long ull;

// Device scratch
__device__ float g_act[4 * 64 * HW];      // [b][co=64][h][w]
__device__ float g_mask[4 * HW * 100];    // [b][pixel][k=25][s=4], softmaxed
__device__ float g_wt2[576 * 112];        // enc w: [t=ci*9+r][s=4][28pad]
__device__ float g_wct[256 * 64];         // comp w: [c][o]

// ---- f32x2 helpers -------------------------------------------------------
__device__ __forceinline__ void ffma2(ull& d, ull a, ull b) {
  asm("fma.rn.f32x2 %0, %1, %2, %0;" : "+l"(d) : "l"(a), "l"(b));
}
__device__ __forceinline__ ull dup2(float v) {
  ull d;
  asm("mov.b64 %0, {%1, %1};" : "=l"(d) : "r"(__float_as_uint(v)));
  return d;
}
__device__ __forceinline__ float lo32(ull d) { return __uint_as_float((unsigned)d); }
__device__ __forceinline__ float hi32(ull d) { return __uint_as_float((unsigned)(d >> 32)); }

// ---------------------------------------------------------------------------
// kW: one-time weight reorganization
// ---------------------------------------------------------------------------
__global__ void __launch_bounds__(256) kW(const float* __restrict__ wc,
                                          const float* __restrict__ we) {
  int idx = blockIdx.x * 256 + threadIdx.x;
  if (idx < 576 * 112) {
    int t = idx / 112;
    int rem = idx - t * 112;
    int s = rem / 28, k = rem - s * 28;
    g_wt2[idx] = (k < 25) ? we[(k * 4 + s) * 576 + t] : 0.f;
  }
  int j = idx - 576 * 112;
  if (j >= 0 && j < 256 * 64) {
    int c = j >> 6, o = j & 63;
    g_wct[j] = wc[o * 256 + c];
  }
}

// ---------------------------------------------------------------------------
// kA: 1x1 conv (256->64) + BN + SiLU, f32x2 packed over output pairs.
// ---------------------------------------------------------------------------
__global__ void __launch_bounds__(128) kA(
    const float* __restrict__ x,
    const float* __restrict__ gma, const float* __restrict__ bet,
    const float* __restrict__ mea, const float* __restrict__ var) {
  __shared__ float xs[64 * 64];
  __shared__ float ws[64 * 64];

  int blk = blockIdx.x;
  int b = blk >> 6;
  int p0 = (blk & 63) << 6;
  int tid = threadIdx.x;
  int pp = tid & 15;   // 4 pixels
  int po = tid >> 4;   // 8 outputs (4 pairs)

  ull acc[4][4];
#pragma unroll
  for (int a = 0; a < 4; a++)
#pragma unroll
    for (int p = 0; p < 4; p++) acc[a][p] = 0ull;

  const float* xb = x + (size_t)(b * 256) * HW + p0;

#pragma unroll 1
  for (int cc = 0; cc < 4; cc++) {
    __syncthreads();
    const float4* xg = (const float4*)(xb + (size_t)cc * 64 * HW);
    float4* xsd = (float4*)xs;
    for (int u = tid; u < 1024; u += 128) {
      int ci = u >> 4, m = u & 15;
      xsd[u] = xg[ci * 1024 + m];
    }
    const float4* wg = (const float4*)(g_wct + cc * 64 * 64);
    float4* wsd = (float4*)ws;
    for (int u = tid; u < 1024; u += 128) wsd[u] = wg[u];
    __syncthreads();

#pragma unroll 4
    for (int ci = 0; ci < 64; ci++) {
      float4 xv = *(const float4*)(xs + ci * 64 + pp * 4);
      ull xd[4] = {dup2(xv.x), dup2(xv.y), dup2(xv.z), dup2(xv.w)};
      const ull* wp = (const ull*)(ws + ci * 64 + po * 8);
#pragma unroll
      for (int op = 0; op < 4; op++) {
        ull w2 = wp[op];
#pragma unroll
        for (int p = 0; p < 4; p++) ffma2(acc[op][p], w2, xd[p]);
      }
    }
  }

  float* actb = g_act + (size_t)(b * 64) * HW + p0 + pp * 4;
#pragma unroll
  for (int op = 0; op < 4; op++) {
    int o = po * 8 + op * 2;
    float inv0 = gma[o] * rsqrtf(var[o] + 1e-5f);
    float off0 = bet[o] - mea[o] * inv0;
    float inv1 = gma[o + 1] * rsqrtf(var[o + 1] + 1e-5f);
    float off1 = bet[o + 1] - mea[o + 1] * inv1;
    float4 r0, r1;
    float v;
    v = lo32(acc[op][0]) * inv0 + off0; r0.x = v / (1.f + __expf(-v));
    v = lo32(acc[op][1]) * inv0 + off0; r0.y = v / (1.f + __expf(-v));
    v = lo32(acc[op][2]) * inv0 + off0; r0.z = v / (1.f + __expf(-v));
    v = lo32(acc[op][3]) * inv0 + off0; r0.w = v / (1.f + __expf(-v));
    v = hi32(acc[op][0]) * inv1 + off1; r1.x = v / (1.f + __expf(-v));
    v = hi32(acc[op][1]) * inv1 + off1; r1.y = v / (1.f + __expf(-v));
    v = hi32(acc[op][2]) * inv1 + off1; r1.z = v / (1.f + __expf(-v));
    v = hi32(acc[op][3]) * inv1 + off1; r1.w = v / (1.f + __expf(-v));
    *(float4*)(actb + (size_t)o * HW) = r0;
    *(float4*)(actb + (size_t)(o + 1) * HW) = r1;
  }
}

// ---------------------------------------------------------------------------
// kB: 3x3 conv (64->100ch) + softmax over k. f32x2 packed over adjacent k.
// ---------------------------------------------------------------------------
__global__ void __launch_bounds__(128, 5) kB() {
  __shared__ float as_[6400];   // act tile [64][10][10]
  __shared__ float ws[4032];    // weight chunk [36][112]

  int b = blockIdx.z;
  int i0 = blockIdx.y << 3, j0 = blockIdx.x << 3;
  int tid = threadIdx.x;
  int s = tid & 3, q = tid >> 2;
  int ty = q >> 3, tx = q & 7;

  for (int idx = tid; idx < 6400; idx += 128) {
    int ci = idx / 100;
    int rem = idx - ci * 100;
    int rr = rem / 10, cc2 = rem - rr * 10;
    int gi = i0 + rr - 1, gj = j0 + cc2 - 1;
    float v = 0.f;
    if ((unsigned)gi < 64u && (unsigned)gj < 64u)
      v = g_act[((size_t)(b * 64 + ci)) * HW + (gi << 6) + gj];
    as_[idx] = v;
  }

  ull a0p[12], a1p[12];
  float a0t = 0.f, a1t = 0.f;
#pragma unroll
  for (int t = 0; t < 12; t++) { a0p[t] = 0ull; a1p[t] = 0ull; }

#pragma unroll 1
  for (int cc = 0; cc < 16; cc++) {
    __syncthreads();
    const float4* src = (const float4*)(g_wt2 + cc * 4032);
    float4* dstw = (float4*)ws;
    for (int u = tid; u < 1008; u += 128) dstw[u] = src[u];
    __syncthreads();
#pragma unroll 1
    for (int cl = 0; cl < 4; cl++) {
      const float* ap = as_ + (cc * 4 + cl) * 100;
#pragma unroll
      for (int r = 0; r < 9; r++) {
        int dy = r / 3, dx = r - dy * 3;
        float v0 = ap[(ty + dy) * 10 + tx + dx];
        float v1 = ap[(ty + 4 + dy) * 10 + tx + dx];
        ull v0d = dup2(v0), v1d = dup2(v1);
        int off = (cl * 9 + r) * 112 + s * 28;
        const ull* wp = (const ull*)(ws + off);
#pragma unroll
        for (int t = 0; t < 12; t++) {
          ull w2 = wp[t];
          ffma2(a0p[t], w2, v0d);
          ffma2(a1p[t], w2, v1d);
        }
        float wl = ws[off + 24];
        a0t += wl * v0;
        a1t += wl * v1;
      }
    }
  }

  float acc0[25], acc1[25];
#pragma unroll
  for (int t = 0; t < 12; t++) {
    acc0[2 * t] = lo32(a0p[t]); acc0[2 * t + 1] = hi32(a0p[t]);
    acc1[2 * t] = lo32(a1p[t]); acc1[2 * t + 1] = hi32(a1p[t]);
  }
  acc0[24] = a0t; acc1[24] = a1t;

  int p0 = (i0 + ty) * 64 + (j0 + tx);
  int p1 = p0 + 256;
  {
    float m = acc0[0];
#pragma unroll
    for (int k = 1; k < 25; k++) m = fmaxf(m, acc0[k]);
    float ssum = 0.f;
#pragma unroll
    for (int k = 0; k < 25; k++) { acc0[k] = __expf(acc0[k] - m); ssum += acc0[k]; }
    float rs = 1.f / ssum;
    float* dst = g_mask + ((size_t)(b * HW + p0)) * 100 + s;
#pragma unroll
    for (int k = 0; k < 25; k++) dst[4 * k] = acc0[k] * rs;
  }
  {
    float m = acc1[0];
#pragma unroll
    for (int k = 1; k < 25; k++) m = fmaxf(m, acc1[k]);
    float ssum = 0.f;
#pragma unroll
    for (int k = 0; k < 25; k++) { acc1[k] = __expf(acc1[k] - m); ssum += acc1[k]; }
    float rs = 1.f / ssum;
    float* dst = g_mask + ((size_t)(b * HW + p1)) * 100 + s;
#pragma unroll
    for (int k = 0; k < 25; k++) dst[4 * k] = acc1[k] * rs;
  }
}

// ---------------------------------------------------------------------------
// kC: 5x5 unfold + mask-weighted sum + pixel shuffle.
// s-packed FFMA2, but x from NON-duplicated smem tile via scalar LDS + dup mov
// (ALU pipe has headroom; smem crossbar traffic back to scalar level).
// 32 channels/block, grid 1024, launch_bounds(128,4).
// ---------------------------------------------------------------------------
__global__ void __launch_bounds__(128, 4) kC(const float* __restrict__ x,
                                             float* __restrict__ out) {
  extern __shared__ float xs[];   // [32][6][68] = 13056 floats
  int gc0 = blockIdx.x << 5;
  int ri = blockIdx.y;
  int b = blockIdx.z;
  int tid = threadIdx.x;
  int r = tid >> 6, j = tid & 63;
  int i = (ri << 1) + r;

  const float* xb = x + ((size_t)(b * 256 + gc0)) * HW;
  for (int u = tid; u < 3072; u += 128) {
    int c = u / 96;
    int rem = u - c * 96;
    int lr = rem >> 4, m = rem & 15;
    int grow = (ri << 1) - 2 + lr;
    float4 v = make_float4(0.f, 0.f, 0.f, 0.f);
    if ((unsigned)grow < 64u)
      v = *(const float4*)(xb + (size_t)c * HW + (grow << 6) + m * 4);
    float* d = xs + c * 408 + lr * 68 + 2 + m * 4;
    *(float2*)d = make_float2(v.x, v.y);
    *(float2*)(d + 2) = make_float2(v.z, v.w);
  }
  // halo cols {0,1,66,67} = zero
  for (int u = tid; u < 384; u += 128) {
    int c = u / 12;
    int rem = u - c * 12;
    int lr = rem >> 1, side = rem & 1;
    *(float2*)(xs + c * 408 + lr * 68 + side * 66) = make_float2(0.f, 0.f);
  }
  __syncthreads();

  // mask pairs -> registers ([pixel][k][s] layout in gmem)
  ull mk01[25], mk23[25];
  const ulonglong2* mp =
      (const ulonglong2*)(g_mask + ((size_t)(b * HW + (i << 6) + j)) * 100);
#pragma unroll
  for (int k = 0; k < 25; k++) {
    ulonglong2 v = mp[k];
    mk01[k] = v.x;   // (s=0, s=1)
    mk23[k] = v.y;   // (s=2, s=3)
  }

  float* ob = out + ((size_t)(b * 256 + gc0) * 128 + (i << 1)) * 128 + (j << 1);

#pragma unroll 1
  for (int c = 0; c < 32; c++) {
    const float* pq = xs + c * 408 + r * 68 + j;
    ull acc01 = 0ull, acc23 = 0ull;
#pragma unroll
    for (int dy = 0; dy < 5; dy++) {
#pragma unroll
      for (int dx = 0; dx < 5; dx++) {
        ull pvv = dup2(pq[dy * 68 + dx]);
        int k = dy * 5 + dx;
        ffma2(acc01, mk01[k], pvv);
        ffma2(acc23, mk23[k], pvv);
      }
    }
    float* op = ob + (size_t)c * 128 * 128;
    *(float2*)op = make_float2(lo32(acc01), hi32(acc01));
    *(float2*)(op + 128) = make_float2(lo32(acc23), hi32(acc23));
  }
}

// ---------------------------------------------------------------------------
extern "C" void kernel_launch(void* const* d_in, const int* in_sizes, int n_in,
                              void* d_out, int out_size) {
  const float* x   = (const float*)d_in[0];
  const float* wc  = (const float*)d_in[1];
  const float* gma = (const float*)d_in[2];
  const float* bet = (const float*)d_in[3];
  const float* mea = (const float*)d_in[4];
  const float* var = (const float*)d_in[5];
  const float* we  = (const float*)d_in[6];
  float* out = (float*)d_out;

  int smC = 32 * 408 * 4;  // 52224
  cudaFuncSetAttribute(kC, cudaFuncAttributeMaxDynamicSharedMemorySize, smC);

  kW<<<(576 * 112 + 256 * 64 + 255) / 256, 256>>>(wc, we);
  kA<<<256, 128>>>(x, gma, bet, mea, var);
  kB<<<dim3(8, 8, 4), 128>>>();
  kC<<<dim3(8, 32, 4), 128, smC>>>(x, out);
}